// round 1
// baseline (speedup 1.0000x reference)
#include <cuda_runtime.h>
#include <cuda_bf16.h>
#include <cstdint>

// Problem constants
#define Bn 8
#define Nn 1024
#define Dn 1024
#define Hn 16
#define DHn 64
#define D3 3072
#define SCALE 0.125f
#define NEGV -1e9f

// Scratch (device globals: allocation-free)
__device__ float g_qkv[(size_t)Bn * Nn * D3];     // 96 MB
__device__ float g_heads[(size_t)Bn * Nn * Dn];   // 32 MB

// ---------------------------------------------------------------------------
// SGEMM: C[M,N] = A[M,K] @ B[K,N] (+ bias), row-major, fp32.
// BM=BN=128, BK=16, TM=TN=8, 256 threads.
// ---------------------------------------------------------------------------
#define BM 128
#define BN 128
#define BK 16
#define TM 8
#define TN 8

__global__ __launch_bounds__(256) void sgemm_kernel(
    const float* __restrict__ A, const float* __restrict__ Bm,
    float* __restrict__ C, const float* __restrict__ bias,
    int M, int Ncols, int K)
{
    __shared__ float As[BK][BM];
    __shared__ float Bs[BK][BN];

    int tid = threadIdx.x;
    int crow = blockIdx.y * BM;
    int ccol = blockIdx.x * BN;
    int threadRow = tid >> 4;   // 0..15
    int threadCol = tid & 15;   // 0..15

    int aRow  = tid >> 2;        // 0..63
    int aCol4 = (tid & 3) * 4;   // 0,4,8,12
    int bRow  = tid >> 5;        // 0..7
    int bCol4 = (tid & 31) * 4;  // 0..124

    float acc[TM][TN];
    #pragma unroll
    for (int i = 0; i < TM; ++i)
        #pragma unroll
        for (int j = 0; j < TN; ++j) acc[i][j] = 0.f;

    const float* Aptr = A + (size_t)crow * K;
    const float* Bptr = Bm + ccol;

    for (int k0 = 0; k0 < K; k0 += BK) {
        #pragma unroll
        for (int off = 0; off < BM; off += 64) {
            float4 t = *(const float4*)&Aptr[(size_t)(aRow + off) * K + k0 + aCol4];
            As[aCol4 + 0][aRow + off] = t.x;
            As[aCol4 + 1][aRow + off] = t.y;
            As[aCol4 + 2][aRow + off] = t.z;
            As[aCol4 + 3][aRow + off] = t.w;
        }
        #pragma unroll
        for (int off = 0; off < BK; off += 8) {
            float4 t = *(const float4*)&Bptr[(size_t)(k0 + bRow + off) * Ncols + bCol4];
            *(float4*)&Bs[bRow + off][bCol4] = t;
        }
        __syncthreads();

        #pragma unroll
        for (int k = 0; k < BK; ++k) {
            float regA[TM], regB[TN];
            #pragma unroll
            for (int i = 0; i < TM; i += 4) {
                float4 t = *(const float4*)&As[k][threadRow * TM + i];
                regA[i] = t.x; regA[i+1] = t.y; regA[i+2] = t.z; regA[i+3] = t.w;
            }
            #pragma unroll
            for (int j = 0; j < TN; j += 4) {
                float4 t = *(const float4*)&Bs[k][threadCol * TN + j];
                regB[j] = t.x; regB[j+1] = t.y; regB[j+2] = t.z; regB[j+3] = t.w;
            }
            #pragma unroll
            for (int i = 0; i < TM; ++i)
                #pragma unroll
                for (int j = 0; j < TN; ++j)
                    acc[i][j] = fmaf(regA[i], regB[j], acc[i][j]);
        }
        __syncthreads();
    }

    #pragma unroll
    for (int i = 0; i < TM; ++i) {
        size_t row = crow + threadRow * TM + i;
        #pragma unroll
        for (int j = 0; j < TN; j += 4) {
            int col = ccol + threadCol * TN + j;
            float4 o;
            o.x = acc[i][j + 0];
            o.y = acc[i][j + 1];
            o.z = acc[i][j + 2];
            o.w = acc[i][j + 3];
            if (bias) {
                o.x += bias[col + 0];
                o.y += bias[col + 1];
                o.z += bias[col + 2];
                o.w += bias[col + 3];
            }
            *(float4*)&C[row * Ncols + col] = o;
        }
    }
}

// ---------------------------------------------------------------------------
// Fused attention: per block = (b, h, 32-query tile).
// Exact softmax over the full key row (matches reference semantics incl.
// masked keys set to exactly -1e9). Writes normalized attn and heads output.
// smem: S[32][1024] + Q[32][68] + KV[64][68]
// ---------------------------------------------------------------------------
#define QT 32
#define KT 64
#define QPAD 68
#define SMEM_ATTN_BYTES ((QT*Nn + QT*QPAD + KT*QPAD) * 4)

__global__ __launch_bounds__(256) void attn_kernel(
    const float* __restrict__ qkv, const int* __restrict__ mask,
    float* __restrict__ attn, float* __restrict__ heads)
{
    extern __shared__ float sm[];
    float* Ss  = sm;                      // QT * 1024
    float* Qs  = Ss + QT * Nn;            // QT * QPAD
    float* KVs = Qs + QT * QPAD;          // KT * QPAD

    int bh = blockIdx.y;
    int b  = bh >> 4;       // / H
    int h  = bh & 15;       // % H
    int q0 = blockIdx.x * QT;
    int tid  = threadIdx.x;
    int lane = tid & 31;
    int wrp  = tid >> 5;

    int kcol = tid & 63;       // key/dh column for compute phases
    int qg   = tid >> 6;       // 0..3 -> query-row group of 8

    const size_t qkv_base = (size_t)b * Nn * D3;

    // Load Q tile (pre-scaled)
    for (int i = tid; i < QT * 16; i += 256) {
        int q = i >> 4, c4 = (i & 15) * 4;
        float4 t = *(const float4*)&qkv[qkv_base + (size_t)(q0 + q) * D3 + h * DHn + c4];
        t.x *= SCALE; t.y *= SCALE; t.z *= SCALE; t.w *= SCALE;
        *(float4*)&Qs[q * QPAD + c4] = t;
    }

    // ---- Phase 1: S = scale * Q K^T with mask -> Ss ----
    for (int kt = 0; kt < Nn / KT; ++kt) {
        __syncthreads();
        // load K tile [64 x 64]
        for (int i = tid; i < KT * 16; i += 256) {
            int r = i >> 4, c4 = (i & 15) * 4;
            float4 t = *(const float4*)&qkv[qkv_base + (size_t)(kt * KT + r) * D3 + Dn + h * DHn + c4];
            *(float4*)&KVs[r * QPAD + c4] = t;
        }
        __syncthreads();

        float acc[8];
        #pragma unroll
        for (int i = 0; i < 8; ++i) acc[i] = 0.f;

        #pragma unroll
        for (int d4 = 0; d4 < 16; ++d4) {
            float4 kv = *(const float4*)&KVs[kcol * QPAD + d4 * 4];
            #pragma unroll
            for (int i = 0; i < 8; ++i) {
                float4 qv = *(const float4*)&Qs[(qg * 8 + i) * QPAD + d4 * 4];
                acc[i] += qv.x * kv.x + qv.y * kv.y + qv.z * kv.z + qv.w * kv.w;
            }
        }

        bool msk = (mask[b * Nn + kt * KT + kcol] == 0);
        #pragma unroll
        for (int i = 0; i < 8; ++i)
            Ss[(qg * 8 + i) * Nn + kt * KT + kcol] = msk ? NEGV : acc[i];
    }
    __syncthreads();

    // ---- Phase 2: exact row softmax; write attn; keep normalized P in Ss ----
    #pragma unroll
    for (int r = wrp * 4; r < wrp * 4 + 4; ++r) {
        float* row = Ss + r * Nn;
        float mx = -3.4e38f;
        for (int k4 = lane; k4 < Nn / 4; k4 += 32) {
            float4 v = *(const float4*)&row[k4 * 4];
            mx = fmaxf(mx, fmaxf(fmaxf(v.x, v.y), fmaxf(v.z, v.w)));
        }
        #pragma unroll
        for (int s = 16; s; s >>= 1) mx = fmaxf(mx, __shfl_xor_sync(0xffffffffu, mx, s));

        float sum = 0.f;
        for (int k4 = lane; k4 < Nn / 4; k4 += 32) {
            float4 v = *(const float4*)&row[k4 * 4];
            v.x = __expf(v.x - mx); v.y = __expf(v.y - mx);
            v.z = __expf(v.z - mx); v.w = __expf(v.w - mx);
            sum += v.x + v.y + v.z + v.w;
            *(float4*)&row[k4 * 4] = v;
        }
        #pragma unroll
        for (int s = 16; s; s >>= 1) sum += __shfl_xor_sync(0xffffffffu, sum, s);

        float inv = 1.f / sum;
        float* arow = attn ? attn + ((size_t)bh * Nn + q0 + r) * Nn : nullptr;
        for (int k4 = lane; k4 < Nn / 4; k4 += 32) {
            float4 v = *(const float4*)&row[k4 * 4];
            v.x *= inv; v.y *= inv; v.z *= inv; v.w *= inv;
            *(float4*)&row[k4 * 4] = v;
            if (arow) *(float4*)&arow[k4 * 4] = v;
        }
    }

    // ---- Phase 3: O = P @ V ----
    float o[8];
    #pragma unroll
    for (int i = 0; i < 8; ++i) o[i] = 0.f;

    for (int kt = 0; kt < Nn / KT; ++kt) {
        __syncthreads();
        // load V tile [64 x 64]
        for (int i = tid; i < KT * 16; i += 256) {
            int r = i >> 4, c4 = (i & 15) * 4;
            float4 t = *(const float4*)&qkv[qkv_base + (size_t)(kt * KT + r) * D3 + 2 * Dn + h * DHn + c4];
            *(float4*)&KVs[r * QPAD + c4] = t;
        }
        __syncthreads();

        #pragma unroll
        for (int j4 = 0; j4 < 16; ++j4) {
            float vv0 = KVs[(j4 * 4 + 0) * QPAD + kcol];
            float vv1 = KVs[(j4 * 4 + 1) * QPAD + kcol];
            float vv2 = KVs[(j4 * 4 + 2) * QPAD + kcol];
            float vv3 = KVs[(j4 * 4 + 3) * QPAD + kcol];
            #pragma unroll
            for (int i = 0; i < 8; ++i) {
                float4 p = *(const float4*)&Ss[(qg * 8 + i) * Nn + kt * KT + j4 * 4];
                o[i] += p.x * vv0 + p.y * vv1 + p.z * vv2 + p.w * vv3;
            }
        }
    }

    // heads layout: [b, n, h, dh] == [b, n, D] (matches transpose-back+reshape)
    #pragma unroll
    for (int i = 0; i < 8; ++i) {
        int q = qg * 8 + i;
        heads[((size_t)b * Nn + q0 + q) * Dn + h * DHn + kcol] = o[i];
    }
}

// ---------------------------------------------------------------------------

extern "C" void kernel_launch(void* const* d_in, const int* in_sizes, int n_in,
                              void* d_out, int out_size)
{
    const float* x     = (const float*)d_in[0];
    const int*   mask  = (const int*)d_in[1];
    const float* w_qkv = (const float*)d_in[2];
    const float* w_out = (const float*)d_in[3];
    const float* b_out = (const float*)d_in[4];

    float* out = (float*)d_out;
    const size_t out_elems  = (size_t)Bn * Nn * Dn;        // 8,388,608
    const size_t attn_elems = (size_t)Bn * Hn * Nn * Nn;   // 134,217,728
    float* attn = ((size_t)out_size >= out_elems + attn_elems) ? out + out_elems : nullptr;

    float* qkv;
    float* heads;
    cudaGetSymbolAddress((void**)&qkv, g_qkv);
    cudaGetSymbolAddress((void**)&heads, g_heads);

    cudaFuncSetAttribute(attn_kernel, cudaFuncAttributeMaxDynamicSharedMemorySize,
                         SMEM_ATTN_BYTES);

    // 1) QKV projection: [8192,1024] @ [1024,3072]
    {
        dim3 grid(D3 / BN, (Bn * Nn) / BM);
        sgemm_kernel<<<grid, 256>>>(x, w_qkv, qkv, nullptr, Bn * Nn, D3, Dn);
    }

    // 2) fused attention (writes attn + heads)
    {
        dim3 grid(Nn / QT, Bn * Hn);
        attn_kernel<<<grid, 256, SMEM_ATTN_BYTES>>>(qkv, mask, attn, heads);
    }

    // 3) output projection with bias: [8192,1024] @ [1024,1024] + b
    {
        dim3 grid(Dn / BN, (Bn * Nn) / BM);
        sgemm_kernel<<<grid, 256>>>(heads, w_out, out, b_out, Bn * Nn, Dn, Dn);
    }
}

// round 3
// speedup vs baseline: 1.2135x; 1.2135x over previous
#include <cuda_runtime.h>
#include <cuda_bf16.h>
#include <cstdint>

// Problem constants
#define Bn 8
#define Nn 1024
#define Dn 1024
#define Hn 16
#define DHn 64
#define D3 3072
#define SCALE 0.125f
#define NEGV -1e9f
#define Kdim 1024

// ---------------------------------------------------------------------------
// Device scratch (allocation-free)
// ---------------------------------------------------------------------------
__device__ float g_qkv[(size_t)Bn * Nn * D3];     // 96 MB fp32
__device__ float g_heads[(size_t)Bn * Nn * Dn];   // 32 MB fp32
__device__ __nv_bfloat16 g_xhi[(size_t)Bn * Nn * Dn];
__device__ __nv_bfloat16 g_xlo[(size_t)Bn * Nn * Dn];
__device__ __nv_bfloat16 g_wqkvThi[(size_t)D3 * Dn];
__device__ __nv_bfloat16 g_wqkvTlo[(size_t)D3 * Dn];
__device__ __nv_bfloat16 g_woutThi[(size_t)Dn * Dn];
__device__ __nv_bfloat16 g_woutTlo[(size_t)Dn * Dn];
__device__ __nv_bfloat16 g_hhi[(size_t)Bn * Nn * Dn];
__device__ __nv_bfloat16 g_hlo[(size_t)Bn * Nn * Dn];

// ---------------------------------------------------------------------------
// PTX helpers (baseline sm_80+ features only — NO tcgen05 on compute_103)
// ---------------------------------------------------------------------------
__device__ __forceinline__ uint32_t smem_u32(const void* p) {
    uint32_t a;
    asm("{ .reg .u64 t; cvta.to.shared.u64 t, %1; cvt.u32.u64 %0, t; }"
        : "=r"(a) : "l"(p));
    return a;
}

#define CP_ASYNC16(dst, gsrc) \
    asm volatile("cp.async.cg.shared.global [%0], [%1], 16;" :: "r"(dst), "l"(gsrc))
#define CP_COMMIT() asm volatile("cp.async.commit_group;" ::: "memory")
#define CP_WAIT2()  asm volatile("cp.async.wait_group 2;" ::: "memory")
#define CP_WAIT1()  asm volatile("cp.async.wait_group 1;" ::: "memory")
#define CP_WAIT0()  asm volatile("cp.async.wait_group 0;" ::: "memory")

#define LDSM_X4(r0, r1, r2, r3, addr) \
    asm volatile("ldmatrix.sync.aligned.m8n8.x4.shared.b16 {%0,%1,%2,%3}, [%4];" \
                 : "=r"(r0), "=r"(r1), "=r"(r2), "=r"(r3) : "r"(addr))

#define MMA16816(d, a, b) \
    asm volatile("mma.sync.aligned.m16n8k16.row.col.f32.bf16.bf16.f32 " \
                 "{%0,%1,%2,%3}, {%4,%5,%6,%7}, {%8,%9}, {%0,%1,%2,%3};" \
                 : "+f"((d)[0]), "+f"((d)[1]), "+f"((d)[2]), "+f"((d)[3]) \
                 : "r"((a)[0]), "r"((a)[1]), "r"((a)[2]), "r"((a)[3]), \
                   "r"((b)[0]), "r"((b)[1]))

// ---------------------------------------------------------------------------
// Split kernels: fp32 -> (bf16 hi, bf16 lo)
// ---------------------------------------------------------------------------
__global__ __launch_bounds__(256) void split_kernel(
    const float4* __restrict__ in, __nv_bfloat162* __restrict__ hi,
    __nv_bfloat162* __restrict__ lo, int n4)
{
    int i = blockIdx.x * 256 + threadIdx.x;
    if (i >= n4) return;
    float4 v = in[i];
    __nv_bfloat16 h0 = __float2bfloat16(v.x), h1 = __float2bfloat16(v.y);
    __nv_bfloat16 h2 = __float2bfloat16(v.z), h3 = __float2bfloat16(v.w);
    __nv_bfloat16 l0 = __float2bfloat16(v.x - __bfloat162float(h0));
    __nv_bfloat16 l1 = __float2bfloat16(v.y - __bfloat162float(h1));
    __nv_bfloat16 l2 = __float2bfloat16(v.z - __bfloat162float(h2));
    __nv_bfloat16 l3 = __float2bfloat16(v.w - __bfloat162float(h3));
    hi[2 * i]     = __halves2bfloat162(h0, h1);
    hi[2 * i + 1] = __halves2bfloat162(h2, h3);
    lo[2 * i]     = __halves2bfloat162(l0, l1);
    lo[2 * i + 1] = __halves2bfloat162(l2, l3);
}

// Transpose + split: in [R][C] fp32 -> out [C][R] bf16 hi/lo
__global__ __launch_bounds__(256) void splitT_kernel(
    const float* __restrict__ in, __nv_bfloat16* __restrict__ hiT,
    __nv_bfloat16* __restrict__ loT, int R, int C)
{
    __shared__ float t[32][33];
    int bx = blockIdx.x * 32;
    int by = blockIdx.y * 32;
    int x = threadIdx.x, y = threadIdx.y;  // 32 x 8
    #pragma unroll
    for (int i = y; i < 32; i += 8)
        t[i][x] = in[(size_t)(by + i) * C + bx + x];
    __syncthreads();
    #pragma unroll
    for (int i = y; i < 32; i += 8) {
        float v = t[x][i];
        __nv_bfloat16 h = __float2bfloat16(v);
        size_t o = (size_t)(bx + i) * R + by + x;
        hiT[o] = h;
        loT[o] = __float2bfloat16(v - __bfloat162float(h));
    }
}

// ---------------------------------------------------------------------------
// bf16-split GEMM on mma.sync (HMMA): C[M,Ncols] = A[M,1024] @ B[1024,Ncols]
// A hi/lo: [M][K] bf16 row-major.  B hi/lo: transposed [Ncols][K] bf16.
// CTA 128x128, 8 warps (warp tile 32x64), K-chunk 32, 3-stage cp.async.
// ---------------------------------------------------------------------------
#define WST   40                       // smem row stride in bf16 (80 B)
#define TILEB (128 * WST * 2)          // 10240 B per [128 x 32] tile
#define STAGEB (4 * TILEB)             // Ah, Al, Bh, Bl
#define NSTAGE 3
#define SMEM_GEMM (NSTAGE * STAGEB)    // 122880 B
#define NCHUNK (Kdim / 32)             // 32

__global__ __launch_bounds__(256, 1) void gemm_mma(
    const __nv_bfloat16* __restrict__ Ahi, const __nv_bfloat16* __restrict__ Alo,
    const __nv_bfloat16* __restrict__ BThi, const __nv_bfloat16* __restrict__ BTlo,
    float* __restrict__ C, const float* __restrict__ bias, int Ncols)
{
    extern __shared__ char smem[];
    const uint32_t sb = smem_u32(smem);
    const int tid = threadIdx.x, wid = tid >> 5, lane = tid & 31;
    const int wm = wid >> 1;        // 0..3  (M offset wm*32)
    const int wn = wid & 1;         // 0..1  (N offset wn*64)
    const int ctaM = blockIdx.y * 128, ctaN = blockIdx.x * 128;

    const __nv_bfloat16* gsrc[4] = {
        Ahi + (size_t)ctaM * Kdim, Alo + (size_t)ctaM * Kdim,
        BThi + (size_t)ctaN * Kdim, BTlo + (size_t)ctaN * Kdim};

    // per-thread cp.async coords: each thread does 2 rows x 1 col16 per tile
    // tile has 512 16B-chunks; 256 threads -> 2 each. chunk = r*4 + c16.
    auto load_chunk = [&](int s, int k0) {
        uint32_t base = sb + s * STAGEB;
        #pragma unroll
        for (int t = 0; t < 4; t++) {
            uint32_t tb = base + t * TILEB;
            const __nv_bfloat16* g = gsrc[t] + k0;
            #pragma unroll
            for (int i = tid; i < 512; i += 256) {
                int r = i >> 2, c = i & 3;
                uint32_t dst = tb + r * (WST * 2) + c * 16;
                size_t gs = __cvta_generic_to_global(g + (size_t)r * Kdim + c * 8);
                CP_ASYNC16(dst, gs);
            }
        }
        CP_COMMIT();
    };

    float acc[2][8][4];
    #pragma unroll
    for (int i = 0; i < 2; i++)
        #pragma unroll
        for (int j = 0; j < 8; j++)
            #pragma unroll
            for (int k = 0; k < 4; k++) acc[i][j][k] = 0.f;

    load_chunk(0, 0);
    load_chunk(1, 32);
    load_chunk(2, 64);

    // precomputed ldmatrix lane offsets (bytes within a tile)
    const int q = lane >> 3, l8 = lane & 7;
    // A: rows m0 + (q&1)*8 + l8, col k (q>>1)*8
    const uint32_t aoff = (uint32_t)((wm * 32 + (q & 1) * 8 + l8) * (WST * 2) + (q >> 1) * 16);
    // B: rows n0 + (q>>1)*8 + l8, col k (q&1)*8
    const uint32_t boff = (uint32_t)((wn * 64 + (q >> 1) * 8 + l8) * (WST * 2) + (q & 1) * 16);

    for (int c = 0; c < NCHUNK; c++) {
        int s = c % NSTAGE;
        if (c < NCHUNK - 2) CP_WAIT2();
        else if (c == NCHUNK - 2) CP_WAIT1();
        else CP_WAIT0();
        __syncthreads();

        uint32_t base = sb + s * STAGEB;
        uint32_t tAh = base, tAl = base + TILEB;
        uint32_t tBh = base + 2 * TILEB, tBl = base + 3 * TILEB;

        #pragma unroll
        for (int kk = 0; kk < 2; kk++) {
            uint32_t ah[2][4], al[2][4], bh[8][2], bl[8][2];
            #pragma unroll
            for (int mf = 0; mf < 2; mf++) {
                uint32_t ao = aoff + mf * 16 * (WST * 2) + kk * 32;
                LDSM_X4(ah[mf][0], ah[mf][1], ah[mf][2], ah[mf][3], tAh + ao);
                LDSM_X4(al[mf][0], al[mf][1], al[mf][2], al[mf][3], tAl + ao);
            }
            #pragma unroll
            for (int nf2 = 0; nf2 < 4; nf2++) {
                uint32_t bo = boff + nf2 * 16 * (WST * 2) + kk * 32;
                LDSM_X4(bh[2*nf2][0], bh[2*nf2][1], bh[2*nf2+1][0], bh[2*nf2+1][1], tBh + bo);
                LDSM_X4(bl[2*nf2][0], bl[2*nf2][1], bl[2*nf2+1][0], bl[2*nf2+1][1], tBl + bo);
            }
            #pragma unroll
            for (int mf = 0; mf < 2; mf++)
                #pragma unroll
                for (int nf = 0; nf < 8; nf++) {
                    MMA16816(acc[mf][nf], ah[mf], bh[nf]);
                    MMA16816(acc[mf][nf], ah[mf], bl[nf]);
                    MMA16816(acc[mf][nf], al[mf], bh[nf]);
                }
        }
        __syncthreads();
        if (c + NSTAGE < NCHUNK) load_chunk(s, (c + NSTAGE) * 32);
    }

    // Epilogue
    #pragma unroll
    for (int mf = 0; mf < 2; mf++) {
        int row = ctaM + wm * 32 + mf * 16 + (lane >> 2);
        #pragma unroll
        for (int nf = 0; nf < 8; nf++) {
            int col = ctaN + wn * 64 + nf * 8 + (lane & 3) * 2;
            float bx = 0.f, by = 0.f;
            if (bias) { bx = bias[col]; by = bias[col + 1]; }
            float2 v0 = {acc[mf][nf][0] + bx, acc[mf][nf][1] + by};
            float2 v1 = {acc[mf][nf][2] + bx, acc[mf][nf][3] + by};
            *(float2*)&C[(size_t)row * Ncols + col] = v0;
            *(float2*)&C[(size_t)(row + 8) * Ncols + col] = v1;
        }
    }
}

// ---------------------------------------------------------------------------
// Fused attention (unchanged): per block = (b, h, 32-query tile).
// ---------------------------------------------------------------------------
#define QT 32
#define KT 64
#define QPAD 68
#define SMEM_ATTN_BYTES ((QT*Nn + QT*QPAD + KT*QPAD) * 4)

__global__ __launch_bounds__(256) void attn_kernel(
    const float* __restrict__ qkv, const int* __restrict__ mask,
    float* __restrict__ attn, float* __restrict__ heads)
{
    extern __shared__ float sm[];
    float* Ss  = sm;
    float* Qs  = Ss + QT * Nn;
    float* KVs = Qs + QT * QPAD;

    int bh = blockIdx.y;
    int b  = bh >> 4;
    int h  = bh & 15;
    int q0 = blockIdx.x * QT;
    int tid  = threadIdx.x;
    int lane = tid & 31;
    int wrp  = tid >> 5;
    int kcol = tid & 63;
    int qg   = tid >> 6;

    const size_t qkv_base = (size_t)b * Nn * D3;

    for (int i = tid; i < QT * 16; i += 256) {
        int qq = i >> 4, c4 = (i & 15) * 4;
        float4 t = *(const float4*)&qkv[qkv_base + (size_t)(q0 + qq) * D3 + h * DHn + c4];
        t.x *= SCALE; t.y *= SCALE; t.z *= SCALE; t.w *= SCALE;
        *(float4*)&Qs[qq * QPAD + c4] = t;
    }

    for (int kt = 0; kt < Nn / KT; ++kt) {
        __syncthreads();
        for (int i = tid; i < KT * 16; i += 256) {
            int r = i >> 4, c4 = (i & 15) * 4;
            float4 t = *(const float4*)&qkv[qkv_base + (size_t)(kt * KT + r) * D3 + Dn + h * DHn + c4];
            *(float4*)&KVs[r * QPAD + c4] = t;
        }
        __syncthreads();

        float acc[8];
        #pragma unroll
        for (int i = 0; i < 8; ++i) acc[i] = 0.f;

        #pragma unroll
        for (int d4 = 0; d4 < 16; ++d4) {
            float4 kv = *(const float4*)&KVs[kcol * QPAD + d4 * 4];
            #pragma unroll
            for (int i = 0; i < 8; ++i) {
                float4 qv = *(const float4*)&Qs[(qg * 8 + i) * QPAD + d4 * 4];
                acc[i] += qv.x * kv.x + qv.y * kv.y + qv.z * kv.z + qv.w * kv.w;
            }
        }

        bool msk = (mask[b * Nn + kt * KT + kcol] == 0);
        #pragma unroll
        for (int i = 0; i < 8; ++i)
            Ss[(qg * 8 + i) * Nn + kt * KT + kcol] = msk ? NEGV : acc[i];
    }
    __syncthreads();

    #pragma unroll
    for (int r = wrp * 4; r < wrp * 4 + 4; ++r) {
        float* row = Ss + r * Nn;
        float mx = -3.4e38f;
        for (int k4 = lane; k4 < Nn / 4; k4 += 32) {
            float4 v = *(const float4*)&row[k4 * 4];
            mx = fmaxf(mx, fmaxf(fmaxf(v.x, v.y), fmaxf(v.z, v.w)));
        }
        #pragma unroll
        for (int s = 16; s; s >>= 1) mx = fmaxf(mx, __shfl_xor_sync(0xffffffffu, mx, s));

        float sum = 0.f;
        for (int k4 = lane; k4 < Nn / 4; k4 += 32) {
            float4 v = *(const float4*)&row[k4 * 4];
            v.x = __expf(v.x - mx); v.y = __expf(v.y - mx);
            v.z = __expf(v.z - mx); v.w = __expf(v.w - mx);
            sum += v.x + v.y + v.z + v.w;
            *(float4*)&row[k4 * 4] = v;
        }
        #pragma unroll
        for (int s = 16; s; s >>= 1) sum += __shfl_xor_sync(0xffffffffu, sum, s);

        float inv = 1.f / sum;
        float* arow = attn ? attn + ((size_t)bh * Nn + q0 + r) * Nn : nullptr;
        for (int k4 = lane; k4 < Nn / 4; k4 += 32) {
            float4 v = *(const float4*)&row[k4 * 4];
            v.x *= inv; v.y *= inv; v.z *= inv; v.w *= inv;
            *(float4*)&row[k4 * 4] = v;
            if (arow) *(float4*)&arow[k4 * 4] = v;
        }
    }

    float o[8];
    #pragma unroll
    for (int i = 0; i < 8; ++i) o[i] = 0.f;

    for (int kt = 0; kt < Nn / KT; ++kt) {
        __syncthreads();
        for (int i = tid; i < KT * 16; i += 256) {
            int r = i >> 4, c4 = (i & 15) * 4;
            float4 t = *(const float4*)&qkv[qkv_base + (size_t)(kt * KT + r) * D3 + 2 * Dn + h * DHn + c4];
            *(float4*)&KVs[r * QPAD + c4] = t;
        }
        __syncthreads();

        #pragma unroll
        for (int j4 = 0; j4 < 16; ++j4) {
            float vv0 = KVs[(j4 * 4 + 0) * QPAD + kcol];
            float vv1 = KVs[(j4 * 4 + 1) * QPAD + kcol];
            float vv2 = KVs[(j4 * 4 + 2) * QPAD + kcol];
            float vv3 = KVs[(j4 * 4 + 3) * QPAD + kcol];
            #pragma unroll
            for (int i = 0; i < 8; ++i) {
                float4 p = *(const float4*)&Ss[(qg * 8 + i) * Nn + kt * KT + j4 * 4];
                o[i] += p.x * vv0 + p.y * vv1 + p.z * vv2 + p.w * vv3;
            }
        }
    }

    #pragma unroll
    for (int i = 0; i < 8; ++i) {
        int qq = qg * 8 + i;
        heads[((size_t)b * Nn + q0 + qq) * Dn + h * DHn + kcol] = o[i];
    }
}

// ---------------------------------------------------------------------------

extern "C" void kernel_launch(void* const* d_in, const int* in_sizes, int n_in,
                              void* d_out, int out_size)
{
    const float* x     = (const float*)d_in[0];
    const int*   mask  = (const int*)d_in[1];
    const float* w_qkv = (const float*)d_in[2];
    const float* w_out = (const float*)d_in[3];
    const float* b_out = (const float*)d_in[4];

    float* out = (float*)d_out;
    const size_t out_elems  = (size_t)Bn * Nn * Dn;
    const size_t attn_elems = (size_t)Bn * Hn * Nn * Nn;
    float* attn = ((size_t)out_size >= out_elems + attn_elems) ? out + out_elems : nullptr;

    float *qkv, *heads;
    __nv_bfloat16 *xhi, *xlo, *wqkvThi, *wqkvTlo, *woutThi, *woutTlo, *hhi, *hlo;
    cudaGetSymbolAddress((void**)&qkv, g_qkv);
    cudaGetSymbolAddress((void**)&heads, g_heads);
    cudaGetSymbolAddress((void**)&xhi, g_xhi);
    cudaGetSymbolAddress((void**)&xlo, g_xlo);
    cudaGetSymbolAddress((void**)&wqkvThi, g_wqkvThi);
    cudaGetSymbolAddress((void**)&wqkvTlo, g_wqkvTlo);
    cudaGetSymbolAddress((void**)&woutThi, g_woutThi);
    cudaGetSymbolAddress((void**)&woutTlo, g_woutTlo);
    cudaGetSymbolAddress((void**)&hhi, g_hhi);
    cudaGetSymbolAddress((void**)&hlo, g_hlo);

    cudaFuncSetAttribute(attn_kernel, cudaFuncAttributeMaxDynamicSharedMemorySize,
                         SMEM_ATTN_BYTES);
    cudaFuncSetAttribute(gemm_mma, cudaFuncAttributeMaxDynamicSharedMemorySize,
                         SMEM_GEMM);

    const int n4x = (Bn * Nn * Dn) / 4;

    // 1) splits
    split_kernel<<<(n4x + 255) / 256, 256>>>((const float4*)x,
                                             (__nv_bfloat162*)xhi, (__nv_bfloat162*)xlo, n4x);
    splitT_kernel<<<dim3(D3 / 32, Dn / 32), dim3(32, 8)>>>(w_qkv, wqkvThi, wqkvTlo, Dn, D3);
    splitT_kernel<<<dim3(Dn / 32, Dn / 32), dim3(32, 8)>>>(w_out, woutThi, woutTlo, Dn, Dn);

    // 2) QKV projection on HMMA: [8192,1024] @ [1024,3072]
    gemm_mma<<<dim3(D3 / 128, (Bn * Nn) / 128), 256, SMEM_GEMM>>>(
        xhi, xlo, wqkvThi, wqkvTlo, qkv, nullptr, D3);

    // 3) fused attention
    {
        dim3 grid(Nn / QT, Bn * Hn);
        attn_kernel<<<grid, 256, SMEM_ATTN_BYTES>>>(qkv, mask, attn, heads);
    }

    // 4) split heads, output projection on HMMA with bias
    split_kernel<<<(n4x + 255) / 256, 256>>>((const float4*)heads,
                                             (__nv_bfloat162*)hhi, (__nv_bfloat162*)hlo, n4x);
    gemm_mma<<<dim3(Dn / 128, (Bn * Nn) / 128), 256, SMEM_GEMM>>>(
        hhi, hlo, woutThi, woutTlo, out, b_out, Dn);
}

// round 4
// speedup vs baseline: 3.2379x; 2.6682x over previous
#include <cuda_runtime.h>
#include <cuda_bf16.h>
#include <cstdint>

// Problem constants
#define Bn 8
#define Nn 1024
#define Dn 1024
#define Hn 16
#define DHn 64
#define D3 3072
#define NEGV -1e9f
#define Kdim 1024

// ---------------------------------------------------------------------------
// Device scratch (allocation-free)
// ---------------------------------------------------------------------------
__device__ float g_qkv[(size_t)Bn * Nn * D3];     // 96 MB fp32
__device__ __nv_bfloat16 g_xhi[(size_t)Bn * Nn * Dn];
__device__ __nv_bfloat16 g_xlo[(size_t)Bn * Nn * Dn];
__device__ __nv_bfloat16 g_wqkvThi[(size_t)D3 * Dn];
__device__ __nv_bfloat16 g_wqkvTlo[(size_t)D3 * Dn];
__device__ __nv_bfloat16 g_woutThi[(size_t)Dn * Dn];
__device__ __nv_bfloat16 g_woutTlo[(size_t)Dn * Dn];
__device__ __nv_bfloat16 g_hhi[(size_t)Bn * Nn * Dn];
__device__ __nv_bfloat16 g_hlo[(size_t)Bn * Nn * Dn];
// per-head bf16 hi/lo [b*h][n][64]
#define HEADELEMS ((size_t)Bn * Hn * Nn * DHn)
__device__ __nv_bfloat16 g_qhi[HEADELEMS];
__device__ __nv_bfloat16 g_qlo[HEADELEMS];
__device__ __nv_bfloat16 g_khi[HEADELEMS];
__device__ __nv_bfloat16 g_klo[HEADELEMS];
__device__ __nv_bfloat16 g_vhi[HEADELEMS];
__device__ __nv_bfloat16 g_vlo[HEADELEMS];

// ---------------------------------------------------------------------------
// PTX helpers (baseline sm_80+ features only)
// ---------------------------------------------------------------------------
__device__ __forceinline__ uint32_t smem_u32(const void* p) {
    uint32_t a;
    asm("{ .reg .u64 t; cvta.to.shared.u64 t, %1; cvt.u32.u64 %0, t; }"
        : "=r"(a) : "l"(p));
    return a;
}

#define CP_ASYNC16(dst, gsrc) \
    asm volatile("cp.async.cg.shared.global [%0], [%1], 16;" :: "r"(dst), "l"(gsrc))
#define CP_COMMIT() asm volatile("cp.async.commit_group;" ::: "memory")
#define CP_WAIT2()  asm volatile("cp.async.wait_group 2;" ::: "memory")
#define CP_WAIT1()  asm volatile("cp.async.wait_group 1;" ::: "memory")
#define CP_WAIT0()  asm volatile("cp.async.wait_group 0;" ::: "memory")

#define LDSM_X4(r0, r1, r2, r3, addr) \
    asm volatile("ldmatrix.sync.aligned.m8n8.x4.shared.b16 {%0,%1,%2,%3}, [%4];" \
                 : "=r"(r0), "=r"(r1), "=r"(r2), "=r"(r3) : "r"(addr))

#define LDSM_X4_T(r0, r1, r2, r3, addr) \
    asm volatile("ldmatrix.sync.aligned.m8n8.x4.trans.shared.b16 {%0,%1,%2,%3}, [%4];" \
                 : "=r"(r0), "=r"(r1), "=r"(r2), "=r"(r3) : "r"(addr))

#define MMA16816(d, a, b) \
    asm volatile("mma.sync.aligned.m16n8k16.row.col.f32.bf16.bf16.f32 " \
                 "{%0,%1,%2,%3}, {%4,%5,%6,%7}, {%8,%9}, {%0,%1,%2,%3};" \
                 : "+f"((d)[0]), "+f"((d)[1]), "+f"((d)[2]), "+f"((d)[3]) \
                 : "r"((a)[0]), "r"((a)[1]), "r"((a)[2]), "r"((a)[3]), \
                   "r"((b)[0]), "r"((b)[1]))

__device__ __forceinline__ uint32_t pack_split(float2 p, uint32_t& lo) {
    __nv_bfloat16 hx = __float2bfloat16(p.x), hy = __float2bfloat16(p.y);
    __nv_bfloat16 lx = __float2bfloat16(p.x - __bfloat162float(hx));
    __nv_bfloat16 ly = __float2bfloat16(p.y - __bfloat162float(hy));
    __nv_bfloat162 hv = __halves2bfloat162(hx, hy);
    __nv_bfloat162 lv = __halves2bfloat162(lx, ly);
    lo = *(uint32_t*)&lv;
    return *(uint32_t*)&hv;
}

// ---------------------------------------------------------------------------
// Split kernels: fp32 -> (bf16 hi, bf16 lo)
// ---------------------------------------------------------------------------
__global__ __launch_bounds__(256) void split_kernel(
    const float4* __restrict__ in, __nv_bfloat162* __restrict__ hi,
    __nv_bfloat162* __restrict__ lo, int n4)
{
    int i = blockIdx.x * 256 + threadIdx.x;
    if (i >= n4) return;
    float4 v = in[i];
    __nv_bfloat16 h0 = __float2bfloat16(v.x), h1 = __float2bfloat16(v.y);
    __nv_bfloat16 h2 = __float2bfloat16(v.z), h3 = __float2bfloat16(v.w);
    __nv_bfloat16 l0 = __float2bfloat16(v.x - __bfloat162float(h0));
    __nv_bfloat16 l1 = __float2bfloat16(v.y - __bfloat162float(h1));
    __nv_bfloat16 l2 = __float2bfloat16(v.z - __bfloat162float(h2));
    __nv_bfloat16 l3 = __float2bfloat16(v.w - __bfloat162float(h3));
    hi[2 * i]     = __halves2bfloat162(h0, h1);
    hi[2 * i + 1] = __halves2bfloat162(h2, h3);
    lo[2 * i]     = __halves2bfloat162(l0, l1);
    lo[2 * i + 1] = __halves2bfloat162(l2, l3);
}

// Transpose + split: in [R][C] fp32 -> out [C][R] bf16 hi/lo
__global__ __launch_bounds__(256) void splitT_kernel(
    const float* __restrict__ in, __nv_bfloat16* __restrict__ hiT,
    __nv_bfloat16* __restrict__ loT, int R, int C)
{
    __shared__ float t[32][33];
    int bx = blockIdx.x * 32;
    int by = blockIdx.y * 32;
    int x = threadIdx.x, y = threadIdx.y;  // 32 x 8
    #pragma unroll
    for (int i = y; i < 32; i += 8)
        t[i][x] = in[(size_t)(by + i) * C + bx + x];
    __syncthreads();
    #pragma unroll
    for (int i = y; i < 32; i += 8) {
        float v = t[x][i];
        __nv_bfloat16 h = __float2bfloat16(v);
        size_t o = (size_t)(bx + i) * R + by + x;
        hiT[o] = h;
        loT[o] = __float2bfloat16(v - __bfloat162float(h));
    }
}

// ---------------------------------------------------------------------------
// Prep: qkv fp32 [b][n][3D] -> per-head bf16 hi/lo [b*h][n][64]
// blockIdx.y = 0 (q, scaled 0.125), 1 (k), 2 (v)
// ---------------------------------------------------------------------------
__global__ __launch_bounds__(256) void prep_kernel(
    const float4* __restrict__ qkv4,
    __nv_bfloat16* __restrict__ qhi, __nv_bfloat16* __restrict__ qlo,
    __nv_bfloat16* __restrict__ khi, __nv_bfloat16* __restrict__ klo,
    __nv_bfloat16* __restrict__ vhi, __nv_bfloat16* __restrict__ vlo)
{
    int s = blockIdx.y;
    int i = blockIdx.x * 256 + threadIdx.x;    // over 8192*16*16
    int d4 = i & 15, h = (i >> 4) & 15, bn = i >> 8;
    float scale = (s == 0) ? 0.125f : 1.0f;
    float4 v = qkv4[(size_t)bn * 768 + s * 256 + h * 16 + d4];
    v.x *= scale; v.y *= scale; v.z *= scale; v.w *= scale;

    __nv_bfloat16 h0 = __float2bfloat16(v.x), h1 = __float2bfloat16(v.y);
    __nv_bfloat16 h2 = __float2bfloat16(v.z), h3 = __float2bfloat16(v.w);
    __nv_bfloat16 l0 = __float2bfloat16(v.x - __bfloat162float(h0));
    __nv_bfloat16 l1 = __float2bfloat16(v.y - __bfloat162float(h1));
    __nv_bfloat16 l2 = __float2bfloat16(v.z - __bfloat162float(h2));
    __nv_bfloat16 l3 = __float2bfloat16(v.w - __bfloat162float(h3));

    __nv_bfloat16* hiP = (s == 0) ? qhi : (s == 1) ? khi : vhi;
    __nv_bfloat16* loP = (s == 0) ? qlo : (s == 1) ? klo : vlo;
    size_t o = (((size_t)(bn >> 10) * 16 + h) * 1024 + (bn & 1023)) * 64 + d4 * 4;
    __nv_bfloat162 hA = __halves2bfloat162(h0, h1), hB = __halves2bfloat162(h2, h3);
    __nv_bfloat162 lA = __halves2bfloat162(l0, l1), lB = __halves2bfloat162(l2, l3);
    *(uint2*)&hiP[o] = make_uint2(*(uint32_t*)&hA, *(uint32_t*)&hB);
    *(uint2*)&loP[o] = make_uint2(*(uint32_t*)&lA, *(uint32_t*)&lB);
}

// ---------------------------------------------------------------------------
// bf16-split GEMM on mma.sync (unchanged from R3)
// ---------------------------------------------------------------------------
#define WST   40
#define TILEB (128 * WST * 2)
#define STAGEB (4 * TILEB)
#define NSTAGE 3
#define SMEM_GEMM (NSTAGE * STAGEB)
#define NCHUNK (Kdim / 32)

__global__ __launch_bounds__(256, 1) void gemm_mma(
    const __nv_bfloat16* __restrict__ Ahi, const __nv_bfloat16* __restrict__ Alo,
    const __nv_bfloat16* __restrict__ BThi, const __nv_bfloat16* __restrict__ BTlo,
    float* __restrict__ C, const float* __restrict__ bias, int Ncols)
{
    extern __shared__ char smem[];
    const uint32_t sb = smem_u32(smem);
    const int tid = threadIdx.x, wid = tid >> 5, lane = tid & 31;
    const int wm = wid >> 1;
    const int wn = wid & 1;
    const int ctaM = blockIdx.y * 128, ctaN = blockIdx.x * 128;

    const __nv_bfloat16* gsrc[4] = {
        Ahi + (size_t)ctaM * Kdim, Alo + (size_t)ctaM * Kdim,
        BThi + (size_t)ctaN * Kdim, BTlo + (size_t)ctaN * Kdim};

    auto load_chunk = [&](int s, int k0) {
        uint32_t base = sb + s * STAGEB;
        #pragma unroll
        for (int t = 0; t < 4; t++) {
            uint32_t tb = base + t * TILEB;
            const __nv_bfloat16* g = gsrc[t] + k0;
            #pragma unroll
            for (int i = tid; i < 512; i += 256) {
                int r = i >> 2, c = i & 3;
                uint32_t dst = tb + r * (WST * 2) + c * 16;
                size_t gs = __cvta_generic_to_global(g + (size_t)r * Kdim + c * 8);
                CP_ASYNC16(dst, gs);
            }
        }
        CP_COMMIT();
    };

    float acc[2][8][4];
    #pragma unroll
    for (int i = 0; i < 2; i++)
        #pragma unroll
        for (int j = 0; j < 8; j++)
            #pragma unroll
            for (int k = 0; k < 4; k++) acc[i][j][k] = 0.f;

    load_chunk(0, 0);
    load_chunk(1, 32);
    load_chunk(2, 64);

    const int q = lane >> 3, l8 = lane & 7;
    const uint32_t aoff = (uint32_t)((wm * 32 + (q & 1) * 8 + l8) * (WST * 2) + (q >> 1) * 16);
    const uint32_t boff = (uint32_t)((wn * 64 + (q >> 1) * 8 + l8) * (WST * 2) + (q & 1) * 16);

    for (int c = 0; c < NCHUNK; c++) {
        int s = c % NSTAGE;
        if (c < NCHUNK - 2) CP_WAIT2();
        else if (c == NCHUNK - 2) CP_WAIT1();
        else CP_WAIT0();
        __syncthreads();

        uint32_t base = sb + s * STAGEB;
        uint32_t tAh = base, tAl = base + TILEB;
        uint32_t tBh = base + 2 * TILEB, tBl = base + 3 * TILEB;

        #pragma unroll
        for (int kk = 0; kk < 2; kk++) {
            uint32_t ah[2][4], al[2][4], bh[8][2], bl[8][2];
            #pragma unroll
            for (int mf = 0; mf < 2; mf++) {
                uint32_t ao = aoff + mf * 16 * (WST * 2) + kk * 32;
                LDSM_X4(ah[mf][0], ah[mf][1], ah[mf][2], ah[mf][3], tAh + ao);
                LDSM_X4(al[mf][0], al[mf][1], al[mf][2], al[mf][3], tAl + ao);
            }
            #pragma unroll
            for (int nf2 = 0; nf2 < 4; nf2++) {
                uint32_t bo = boff + nf2 * 16 * (WST * 2) + kk * 32;
                LDSM_X4(bh[2*nf2][0], bh[2*nf2][1], bh[2*nf2+1][0], bh[2*nf2+1][1], tBh + bo);
                LDSM_X4(bl[2*nf2][0], bl[2*nf2][1], bl[2*nf2+1][0], bl[2*nf2+1][1], tBl + bo);
            }
            #pragma unroll
            for (int mf = 0; mf < 2; mf++)
                #pragma unroll
                for (int nf = 0; nf < 8; nf++) {
                    MMA16816(acc[mf][nf], ah[mf], bh[nf]);
                    MMA16816(acc[mf][nf], ah[mf], bl[nf]);
                    MMA16816(acc[mf][nf], al[mf], bh[nf]);
                }
        }
        __syncthreads();
        if (c + NSTAGE < NCHUNK) load_chunk(s, (c + NSTAGE) * 32);
    }

    #pragma unroll
    for (int mf = 0; mf < 2; mf++) {
        int row = ctaM + wm * 32 + mf * 16 + (lane >> 2);
        #pragma unroll
        for (int nf = 0; nf < 8; nf++) {
            int col = ctaN + wn * 64 + nf * 8 + (lane & 3) * 2;
            float bx = 0.f, by = 0.f;
            if (bias) { bx = bias[col]; by = bias[col + 1]; }
            float2 v0 = {acc[mf][nf][0] + bx, acc[mf][nf][1] + by};
            float2 v1 = {acc[mf][nf][2] + bx, acc[mf][nf][3] + by};
            *(float2*)&C[(size_t)row * Ncols + col] = v0;
            *(float2*)&C[(size_t)(row + 8) * Ncols + col] = v1;
        }
    }
}

// ---------------------------------------------------------------------------
// Tensor-core attention: CTA = (32-query tile, b*h). 8 warps, 256 threads.
// S tile [32][1024] fp32 in smem (row stride 1036: conflict-free).
// Phase1: S = Qhi/lo @ K^T (bf16-split HMMA).  Phase2: masked softmax (exact).
// Phase3: O = P @ V (A-frags built from fp32 S, V via ldmatrix.trans).
// ---------------------------------------------------------------------------
#define SROW 1036
#define SBYTES (32 * SROW * 4)             // 132608
#define KSTRIDE 144                        // padded row: 64 bf16 -> 144 B
#define STG_TILE (128 * KSTRIDE)           // 18432
#define STG_SIZE (2 * STG_TILE)            // hi+lo
#define OFF_STG0 SBYTES
#define OFF_STG1 (SBYTES + STG_SIZE)
#define OFF_MASK (SBYTES + 2 * STG_SIZE)
#define SMEM_ATTN (OFF_MASK + 4096)        // 210432

__global__ __launch_bounds__(256, 1) void attn_mma(
    const __nv_bfloat16* __restrict__ qhi, const __nv_bfloat16* __restrict__ qlo,
    const __nv_bfloat16* __restrict__ khi, const __nv_bfloat16* __restrict__ klo,
    const __nv_bfloat16* __restrict__ vhi, const __nv_bfloat16* __restrict__ vlo,
    const int* __restrict__ mask, float* __restrict__ attn,
    __nv_bfloat16* __restrict__ hhi, __nv_bfloat16* __restrict__ hlo)
{
    extern __shared__ char smem[];
    float* S = (float*)smem;
    const uint32_t sb = smem_u32(smem);
    const int tid = threadIdx.x, wid = tid >> 5, lane = tid & 31;
    const int q8 = lane >> 3, l8 = lane & 7;
    const int bh = blockIdx.y, b = bh >> 4, h = bh & 15;
    const int q0 = blockIdx.x * 32;
    const size_t head_base = (size_t)bh * Nn * DHn;

    auto load_tile = [&](const __nv_bfloat16* hiP, const __nv_bfloat16* loP,
                         int tile, uint32_t stgoff) {
        #pragma unroll 4
        for (int i = tid; i < 2048; i += 256) {
            int bsel = i >> 10, r = (i >> 3) & 127, c = i & 7;
            const __nv_bfloat16* src = (bsel ? loP : hiP) + head_base +
                                       (size_t)(tile * 128 + r) * 64 + c * 8;
            uint32_t dst = sb + stgoff + bsel * STG_TILE + r * KSTRIDE + c * 16;
            CP_ASYNC16(dst, __cvta_generic_to_global(src));
        }
        CP_COMMIT();
    };

    // stage Q (hi/lo) into stage1, K tile 0 into stage0
    #pragma unroll
    for (int i = tid; i < 512; i += 256) {
        int bsel = i >> 8, r = (i >> 3) & 31, c = i & 7;
        const __nv_bfloat16* src = (bsel ? qlo : qhi) + head_base +
                                   (size_t)(q0 + r) * 64 + c * 8;
        uint32_t dst = sb + OFF_STG1 + bsel * 4608 + r * KSTRIDE + c * 16;
        CP_ASYNC16(dst, __cvta_generic_to_global(src));
    }
    CP_COMMIT();
    load_tile(khi, klo, 0, OFF_STG0);

    // mask -> smem
    {
        int4 mv = ((const int4*)(mask + b * Nn))[tid];
        ((int4*)(smem + OFF_MASK))[tid] = mv;
    }

    const int wm = wid & 1, wn = wid >> 1;

    // Q fragments
    uint32_t qfh[4][4], qfl[4][4];
    CP_WAIT1();
    __syncthreads();
    {
        uint32_t qhb = sb + OFF_STG1, qlb = sb + OFF_STG1 + 4608;
        #pragma unroll
        for (int kk = 0; kk < 4; kk++) {
            uint32_t ao = (uint32_t)((wm * 16 + (q8 & 1) * 8 + l8) * KSTRIDE +
                                     (q8 >> 1) * 16 + kk * 32);
            LDSM_X4(qfh[kk][0], qfh[kk][1], qfh[kk][2], qfh[kk][3], qhb + ao);
            LDSM_X4(qfl[kk][0], qfl[kk][1], qfl[kk][2], qfl[kk][3], qlb + ao);
        }
    }
    __syncthreads();                 // stage1 free
    load_tile(khi, klo, 1, OFF_STG1);

    // ---- Phase 1: S = Q K^T ----
    for (int kt = 0; kt < 8; kt++) {
        if (kt == 7) CP_WAIT0(); else CP_WAIT1();
        __syncthreads();
        uint32_t stg = sb + ((kt & 1) ? OFF_STG1 : OFF_STG0);
        uint32_t khb = stg, klb = stg + STG_TILE;

        float acc[4][4];
        #pragma unroll
        for (int i = 0; i < 4; i++)
            #pragma unroll
            for (int j = 0; j < 4; j++) acc[i][j] = 0.f;

        #pragma unroll
        for (int kk = 0; kk < 4; kk++) {
            uint32_t bfh[4][2], bfl[4][2];
            #pragma unroll
            for (int pr = 0; pr < 2; pr++) {
                uint32_t bo = (uint32_t)((wn * 32 + pr * 16 + (q8 >> 1) * 8 + l8) * KSTRIDE +
                                         (q8 & 1) * 16 + kk * 32);
                LDSM_X4(bfh[2*pr][0], bfh[2*pr][1], bfh[2*pr+1][0], bfh[2*pr+1][1], khb + bo);
                LDSM_X4(bfl[2*pr][0], bfl[2*pr][1], bfl[2*pr+1][0], bfl[2*pr+1][1], klb + bo);
            }
            #pragma unroll
            for (int nf = 0; nf < 4; nf++) {
                MMA16816(acc[nf], qfh[kk], bfh[nf]);
                MMA16816(acc[nf], qfh[kk], bfl[nf]);
                MMA16816(acc[nf], qfl[kk], bfh[nf]);
            }
        }
        int r0 = wm * 16 + (lane >> 2);
        #pragma unroll
        for (int nf = 0; nf < 4; nf++) {
            int col = kt * 128 + wn * 32 + nf * 8 + (lane & 3) * 2;
            *(float2*)&S[r0 * SROW + col]       = make_float2(acc[nf][0], acc[nf][1]);
            *(float2*)&S[(r0 + 8) * SROW + col] = make_float2(acc[nf][2], acc[nf][3]);
        }
        __syncthreads();
        if (kt + 2 < 8)      load_tile(khi, klo, kt + 2, (kt & 1) ? OFF_STG1 : OFF_STG0);
        else if (kt == 6)    load_tile(vhi, vlo, 0, OFF_STG0);   // prefetch V0
        else                 load_tile(vhi, vlo, 1, OFF_STG1);   // kt==7: V1
    }

    // ---- Phase 2: masked softmax (V loads in flight) ----
    {
        const int4* msk4 = (const int4*)(smem + OFF_MASK);
        #pragma unroll
        for (int rr = 0; rr < 4; rr++) {
            int r = wid * 4 + rr;
            float* row = S + r * SROW;
            float mx = -3.4e38f;
            for (int k4 = lane; k4 < 256; k4 += 32) {
                float4 v = *(float4*)&row[k4 * 4];
                int4 m = msk4[k4];
                v.x = m.x ? v.x : NEGV; v.y = m.y ? v.y : NEGV;
                v.z = m.z ? v.z : NEGV; v.w = m.w ? v.w : NEGV;
                mx = fmaxf(mx, fmaxf(fmaxf(v.x, v.y), fmaxf(v.z, v.w)));
            }
            #pragma unroll
            for (int s = 16; s; s >>= 1) mx = fmaxf(mx, __shfl_xor_sync(0xffffffffu, mx, s));

            float sum = 0.f;
            for (int k4 = lane; k4 < 256; k4 += 32) {
                float4 v = *(float4*)&row[k4 * 4];
                int4 m = msk4[k4];
                v.x = m.x ? v.x : NEGV; v.y = m.y ? v.y : NEGV;
                v.z = m.z ? v.z : NEGV; v.w = m.w ? v.w : NEGV;
                v.x = __expf(v.x - mx); v.y = __expf(v.y - mx);
                v.z = __expf(v.z - mx); v.w = __expf(v.w - mx);
                sum += v.x + v.y + v.z + v.w;
                *(float4*)&row[k4 * 4] = v;
            }
            #pragma unroll
            for (int s = 16; s; s >>= 1) sum += __shfl_xor_sync(0xffffffffu, sum, s);

            float inv = 1.f / sum;
            float* arow = attn ? attn + ((size_t)bh * Nn + q0 + r) * Nn : nullptr;
            for (int k4 = lane; k4 < 256; k4 += 32) {
                float4 v = *(float4*)&row[k4 * 4];
                v.x *= inv; v.y *= inv; v.z *= inv; v.w *= inv;
                *(float4*)&row[k4 * 4] = v;
                if (arow) *(float4*)&arow[k4 * 4] = v;
            }
        }
    }
    __syncthreads();

    // ---- Phase 3: O = P V ----
    const int wm2 = wid & 1, wn2 = wid >> 1;
    float oacc[2][4];
    #pragma unroll
    for (int i = 0; i < 2; i++)
        #pragma unroll
        for (int j = 0; j < 4; j++) oacc[i][j] = 0.f;

    const int r0 = wm2 * 16 + (lane >> 2);
    for (int vt = 0; vt < 8; vt++) {
        if (vt == 7) CP_WAIT0(); else CP_WAIT1();
        __syncthreads();
        uint32_t stg = sb + ((vt & 1) ? OFF_STG1 : OFF_STG0);
        uint32_t vhb = stg, vlb = stg + STG_TILE;

        #pragma unroll
        for (int kk = 0; kk < 8; kk++) {
            int kc = vt * 128 + kk * 16 + (lane & 3) * 2;
            float2 p00 = *(float2*)&S[r0 * SROW + kc];
            float2 p01 = *(float2*)&S[r0 * SROW + kc + 8];
            float2 p10 = *(float2*)&S[(r0 + 8) * SROW + kc];
            float2 p11 = *(float2*)&S[(r0 + 8) * SROW + kc + 8];
            uint32_t ah[4], al[4];
            ah[0] = pack_split(p00, al[0]);
            ah[1] = pack_split(p10, al[1]);
            ah[2] = pack_split(p01, al[2]);
            ah[3] = pack_split(p11, al[3]);

            uint32_t vo = (uint32_t)((kk * 16 + (q8 & 1) * 8 + l8) * KSTRIDE +
                                     wn2 * 32 + (q8 >> 1) * 16);
            uint32_t bh0[2], bh1[2], bl0[2], bl1[2];
            LDSM_X4_T(bh0[0], bh0[1], bh1[0], bh1[1], vhb + vo);
            LDSM_X4_T(bl0[0], bl0[1], bl1[0], bl1[1], vlb + vo);

            MMA16816(oacc[0], ah, bh0);
            MMA16816(oacc[0], ah, bl0);
            MMA16816(oacc[0], al, bh0);
            MMA16816(oacc[1], ah, bh1);
            MMA16816(oacc[1], ah, bl1);
            MMA16816(oacc[1], al, bh1);
        }
        __syncthreads();
        if (vt + 2 < 8) load_tile(vhi, vlo, vt + 2, (vt & 1) ? OFF_STG1 : OFF_STG0);
    }

    // epilogue: write heads as bf16 hi/lo  [token][D] with D = h*64 + dh
    #pragma unroll
    for (int nt = 0; nt < 2; nt++) {
        int col = wn2 * 16 + nt * 8 + (lane & 3) * 2;
        size_t di0 = ((size_t)(b * Nn) + q0 + r0) * Dn + h * 64 + col;
        size_t di1 = di0 + 8 * Dn;
        uint32_t lo0, lo1;
        uint32_t hi0 = pack_split(make_float2(oacc[nt][0], oacc[nt][1]), lo0);
        uint32_t hi1 = pack_split(make_float2(oacc[nt][2], oacc[nt][3]), lo1);
        *(uint32_t*)&hhi[di0] = hi0;
        *(uint32_t*)&hlo[di0] = lo0;
        *(uint32_t*)&hhi[di1] = hi1;
        *(uint32_t*)&hlo[di1] = lo1;
    }
}

// ---------------------------------------------------------------------------

extern "C" void kernel_launch(void* const* d_in, const int* in_sizes, int n_in,
                              void* d_out, int out_size)
{
    const float* x     = (const float*)d_in[0];
    const int*   mask  = (const int*)d_in[1];
    const float* w_qkv = (const float*)d_in[2];
    const float* w_out = (const float*)d_in[3];
    const float* b_out = (const float*)d_in[4];

    float* out = (float*)d_out;
    const size_t out_elems  = (size_t)Bn * Nn * Dn;
    const size_t attn_elems = (size_t)Bn * Hn * Nn * Nn;
    float* attn = ((size_t)out_size >= out_elems + attn_elems) ? out + out_elems : nullptr;

    float* qkv;
    __nv_bfloat16 *xhi, *xlo, *wqkvThi, *wqkvTlo, *woutThi, *woutTlo, *hhi, *hlo;
    __nv_bfloat16 *qhi, *qlo, *khi, *klo, *vhi, *vlo;
    cudaGetSymbolAddress((void**)&qkv, g_qkv);
    cudaGetSymbolAddress((void**)&xhi, g_xhi);
    cudaGetSymbolAddress((void**)&xlo, g_xlo);
    cudaGetSymbolAddress((void**)&wqkvThi, g_wqkvThi);
    cudaGetSymbolAddress((void**)&wqkvTlo, g_wqkvTlo);
    cudaGetSymbolAddress((void**)&woutThi, g_woutThi);
    cudaGetSymbolAddress((void**)&woutTlo, g_woutTlo);
    cudaGetSymbolAddress((void**)&hhi, g_hhi);
    cudaGetSymbolAddress((void**)&hlo, g_hlo);
    cudaGetSymbolAddress((void**)&qhi, g_qhi);
    cudaGetSymbolAddress((void**)&qlo, g_qlo);
    cudaGetSymbolAddress((void**)&khi, g_khi);
    cudaGetSymbolAddress((void**)&klo, g_klo);
    cudaGetSymbolAddress((void**)&vhi, g_vhi);
    cudaGetSymbolAddress((void**)&vlo, g_vlo);

    cudaFuncSetAttribute(gemm_mma, cudaFuncAttributeMaxDynamicSharedMemorySize, SMEM_GEMM);
    cudaFuncSetAttribute(attn_mma, cudaFuncAttributeMaxDynamicSharedMemorySize, SMEM_ATTN);

    const int n4x = (Bn * Nn * Dn) / 4;

    // 1) splits
    split_kernel<<<(n4x + 255) / 256, 256>>>((const float4*)x,
                                             (__nv_bfloat162*)xhi, (__nv_bfloat162*)xlo, n4x);
    splitT_kernel<<<dim3(D3 / 32, Dn / 32), dim3(32, 8)>>>(w_qkv, wqkvThi, wqkvTlo, Dn, D3);
    splitT_kernel<<<dim3(Dn / 32, Dn / 32), dim3(32, 8)>>>(w_out, woutThi, woutTlo, Dn, Dn);

    // 2) QKV projection on HMMA
    gemm_mma<<<dim3(D3 / 128, (Bn * Nn) / 128), 256, SMEM_GEMM>>>(
        xhi, xlo, wqkvThi, wqkvTlo, qkv, nullptr, D3);

    // 3) prep per-head bf16 hi/lo tensors
    prep_kernel<<<dim3((Bn * Nn * Hn * 16) / 256, 3), 256>>>(
        (const float4*)qkv, qhi, qlo, khi, klo, vhi, vlo);

    // 4) tensor-core attention (writes attn + hhi/hlo)
    attn_mma<<<dim3(Nn / 32, Bn * Hn), 256, SMEM_ATTN>>>(
        qhi, qlo, khi, klo, vhi, vlo, mask, attn, hhi, hlo);

    // 5) output projection on HMMA with bias
    gemm_mma<<<dim3(Dn / 128, (Bn * Nn) / 128), 256, SMEM_GEMM>>>(
        hhi, hlo, woutThi, woutTlo, out, b_out, Dn);
}

// round 5
// speedup vs baseline: 3.5810x; 1.1060x over previous
#include <cuda_runtime.h>
#include <cuda_bf16.h>
#include <cstdint>

// Problem constants
#define Bn 8
#define Nn 1024
#define Dn 1024
#define Hn 16
#define DHn 64
#define D3 3072
#define NEGV -1e9f
#define Kdim 1024

// ---------------------------------------------------------------------------
// Device scratch (allocation-free)
// ---------------------------------------------------------------------------
__device__ __nv_bfloat16 g_xhi[(size_t)Bn * Nn * Dn];
__device__ __nv_bfloat16 g_xlo[(size_t)Bn * Nn * Dn];
__device__ __nv_bfloat16 g_wqkvThi[(size_t)D3 * Dn];
__device__ __nv_bfloat16 g_wqkvTlo[(size_t)D3 * Dn];
__device__ __nv_bfloat16 g_woutThi[(size_t)Dn * Dn];
__device__ __nv_bfloat16 g_woutTlo[(size_t)Dn * Dn];
__device__ __nv_bfloat16 g_hhi[(size_t)Bn * Nn * Dn];
__device__ __nv_bfloat16 g_hlo[(size_t)Bn * Nn * Dn];
#define HEADELEMS ((size_t)Bn * Hn * Nn * DHn)
__device__ __nv_bfloat16 g_qhi[HEADELEMS];
__device__ __nv_bfloat16 g_qlo[HEADELEMS];
__device__ __nv_bfloat16 g_khi[HEADELEMS];
__device__ __nv_bfloat16 g_klo[HEADELEMS];
__device__ __nv_bfloat16 g_vhi[HEADELEMS];
__device__ __nv_bfloat16 g_vlo[HEADELEMS];

// ---------------------------------------------------------------------------
// PTX helpers (baseline sm_80+ features only)
// ---------------------------------------------------------------------------
__device__ __forceinline__ uint32_t smem_u32(const void* p) {
    uint32_t a;
    asm("{ .reg .u64 t; cvta.to.shared.u64 t, %1; cvt.u32.u64 %0, t; }"
        : "=r"(a) : "l"(p));
    return a;
}

#define CP_ASYNC16(dst, gsrc) \
    asm volatile("cp.async.cg.shared.global [%0], [%1], 16;" :: "r"(dst), "l"(gsrc))
#define CP_COMMIT() asm volatile("cp.async.commit_group;" ::: "memory")
#define CP_WAIT1()  asm volatile("cp.async.wait_group 1;" ::: "memory")
#define CP_WAIT0()  asm volatile("cp.async.wait_group 0;" ::: "memory")

#define LDSM_X4(r0, r1, r2, r3, addr) \
    asm volatile("ldmatrix.sync.aligned.m8n8.x4.shared.b16 {%0,%1,%2,%3}, [%4];" \
                 : "=r"(r0), "=r"(r1), "=r"(r2), "=r"(r3) : "r"(addr))

#define LDSM_X4_T(r0, r1, r2, r3, addr) \
    asm volatile("ldmatrix.sync.aligned.m8n8.x4.trans.shared.b16 {%0,%1,%2,%3}, [%4];" \
                 : "=r"(r0), "=r"(r1), "=r"(r2), "=r"(r3) : "r"(addr))

#define MMA16816(d, a, b) \
    asm volatile("mma.sync.aligned.m16n8k16.row.col.f32.bf16.bf16.f32 " \
                 "{%0,%1,%2,%3}, {%4,%5,%6,%7}, {%8,%9}, {%0,%1,%2,%3};" \
                 : "+f"((d)[0]), "+f"((d)[1]), "+f"((d)[2]), "+f"((d)[3]) \
                 : "r"((a)[0]), "r"((a)[1]), "r"((a)[2]), "r"((a)[3]), \
                   "r"((b)[0]), "r"((b)[1]))

__device__ __forceinline__ uint32_t pack_split(float2 p, uint32_t& lo) {
    __nv_bfloat16 hx = __float2bfloat16(p.x), hy = __float2bfloat16(p.y);
    __nv_bfloat16 lx = __float2bfloat16(p.x - __bfloat162float(hx));
    __nv_bfloat16 ly = __float2bfloat16(p.y - __bfloat162float(hy));
    __nv_bfloat162 hv = __halves2bfloat162(hx, hy);
    __nv_bfloat162 lv = __halves2bfloat162(lx, ly);
    lo = *(uint32_t*)&lv;
    return *(uint32_t*)&hv;
}

// ---------------------------------------------------------------------------
// Split kernels
// ---------------------------------------------------------------------------
__global__ __launch_bounds__(256) void split_kernel(
    const float4* __restrict__ in, __nv_bfloat162* __restrict__ hi,
    __nv_bfloat162* __restrict__ lo, int n4)
{
    int i = blockIdx.x * 256 + threadIdx.x;
    if (i >= n4) return;
    float4 v = in[i];
    __nv_bfloat16 h0 = __float2bfloat16(v.x), h1 = __float2bfloat16(v.y);
    __nv_bfloat16 h2 = __float2bfloat16(v.z), h3 = __float2bfloat16(v.w);
    __nv_bfloat16 l0 = __float2bfloat16(v.x - __bfloat162float(h0));
    __nv_bfloat16 l1 = __float2bfloat16(v.y - __bfloat162float(h1));
    __nv_bfloat16 l2 = __float2bfloat16(v.z - __bfloat162float(h2));
    __nv_bfloat16 l3 = __float2bfloat16(v.w - __bfloat162float(h3));
    hi[2 * i]     = __halves2bfloat162(h0, h1);
    hi[2 * i + 1] = __halves2bfloat162(h2, h3);
    lo[2 * i]     = __halves2bfloat162(l0, l1);
    lo[2 * i + 1] = __halves2bfloat162(l2, l3);
}

__global__ __launch_bounds__(256) void splitT_kernel(
    const float* __restrict__ in, __nv_bfloat16* __restrict__ hiT,
    __nv_bfloat16* __restrict__ loT, int R, int C)
{
    __shared__ float t[32][33];
    int bx = blockIdx.x * 32;
    int by = blockIdx.y * 32;
    int x = threadIdx.x, y = threadIdx.y;  // 32 x 8
    #pragma unroll
    for (int i = y; i < 32; i += 8)
        t[i][x] = in[(size_t)(by + i) * C + bx + x];
    __syncthreads();
    #pragma unroll
    for (int i = y; i < 32; i += 8) {
        float v = t[x][i];
        __nv_bfloat16 h = __float2bfloat16(v);
        size_t o = (size_t)(bx + i) * R + by + x;
        hiT[o] = h;
        loT[o] = __float2bfloat16(v - __bfloat162float(h));
    }
}

// ---------------------------------------------------------------------------
// bf16-split GEMM on mma.sync. 2-stage pipeline, 2 CTAs/SM target.
// mode 0: C fp32 (+bias).  mode 1: split-write per-head q(×0.125)/k/v hi/lo.
// ---------------------------------------------------------------------------
#define WST   40
#define TILEB (128 * WST * 2)
#define STAGEB (4 * TILEB)
#define NSTAGE 2
#define SMEM_GEMM (NSTAGE * STAGEB)    // 81920
#define NCHUNK (Kdim / 32)

__global__ __launch_bounds__(256, 2) void gemm_mma(
    const __nv_bfloat16* __restrict__ Ahi, const __nv_bfloat16* __restrict__ Alo,
    const __nv_bfloat16* __restrict__ BThi, const __nv_bfloat16* __restrict__ BTlo,
    float* __restrict__ C, const float* __restrict__ bias, int Ncols, int mode,
    __nv_bfloat16* __restrict__ qhi, __nv_bfloat16* __restrict__ qlo,
    __nv_bfloat16* __restrict__ khi, __nv_bfloat16* __restrict__ klo,
    __nv_bfloat16* __restrict__ vhi, __nv_bfloat16* __restrict__ vlo)
{
    extern __shared__ char smem[];
    const uint32_t sb = smem_u32(smem);
    const int tid = threadIdx.x, wid = tid >> 5, lane = tid & 31;
    const int wm = wid >> 1;
    const int wn = wid & 1;
    const int ctaM = blockIdx.y * 128, ctaN = blockIdx.x * 128;

    const __nv_bfloat16* gsrc[4] = {
        Ahi + (size_t)ctaM * Kdim, Alo + (size_t)ctaM * Kdim,
        BThi + (size_t)ctaN * Kdim, BTlo + (size_t)ctaN * Kdim};

    auto load_chunk = [&](int s, int k0) {
        uint32_t base = sb + s * STAGEB;
        #pragma unroll
        for (int t = 0; t < 4; t++) {
            uint32_t tb = base + t * TILEB;
            const __nv_bfloat16* g = gsrc[t] + k0;
            #pragma unroll
            for (int i = tid; i < 512; i += 256) {
                int r = i >> 2, c = i & 3;
                uint32_t dst = tb + r * (WST * 2) + c * 16;
                size_t gs = __cvta_generic_to_global(g + (size_t)r * Kdim + c * 8);
                CP_ASYNC16(dst, gs);
            }
        }
        CP_COMMIT();
    };

    float acc[2][8][4];
    #pragma unroll
    for (int i = 0; i < 2; i++)
        #pragma unroll
        for (int j = 0; j < 8; j++)
            #pragma unroll
            for (int k = 0; k < 4; k++) acc[i][j][k] = 0.f;

    load_chunk(0, 0);
    load_chunk(1, 32);

    const int q = lane >> 3, l8 = lane & 7;
    const uint32_t aoff = (uint32_t)((wm * 32 + (q & 1) * 8 + l8) * (WST * 2) + (q >> 1) * 16);
    const uint32_t boff = (uint32_t)((wn * 64 + (q >> 1) * 8 + l8) * (WST * 2) + (q & 1) * 16);

    for (int c = 0; c < NCHUNK; c++) {
        int s = c & 1;
        if (c == NCHUNK - 1) CP_WAIT0(); else CP_WAIT1();
        __syncthreads();

        uint32_t base = sb + s * STAGEB;
        uint32_t tAh = base, tAl = base + TILEB;
        uint32_t tBh = base + 2 * TILEB, tBl = base + 3 * TILEB;

        #pragma unroll
        for (int kk = 0; kk < 2; kk++) {
            uint32_t ah[2][4], al[2][4];
            #pragma unroll
            for (int mf = 0; mf < 2; mf++) {
                uint32_t ao = aoff + mf * 16 * (WST * 2) + kk * 32;
                LDSM_X4(ah[mf][0], ah[mf][1], ah[mf][2], ah[mf][3], tAh + ao);
                LDSM_X4(al[mf][0], al[mf][1], al[mf][2], al[mf][3], tAl + ao);
            }
            #pragma unroll
            for (int nf2 = 0; nf2 < 4; nf2++) {
                uint32_t bh0[2], bh1[2], bl0[2], bl1[2];
                uint32_t bo = boff + nf2 * 16 * (WST * 2) + kk * 32;
                LDSM_X4(bh0[0], bh0[1], bh1[0], bh1[1], tBh + bo);
                LDSM_X4(bl0[0], bl0[1], bl1[0], bl1[1], tBl + bo);
                int n0 = 2 * nf2, n1 = 2 * nf2 + 1;
                // term-major interleave: 4 independent acc chains
                MMA16816(acc[0][n0], ah[0], bh0);
                MMA16816(acc[0][n1], ah[0], bh1);
                MMA16816(acc[1][n0], ah[1], bh0);
                MMA16816(acc[1][n1], ah[1], bh1);
                MMA16816(acc[0][n0], ah[0], bl0);
                MMA16816(acc[0][n1], ah[0], bl1);
                MMA16816(acc[1][n0], ah[1], bl0);
                MMA16816(acc[1][n1], ah[1], bl1);
                MMA16816(acc[0][n0], al[0], bh0);
                MMA16816(acc[0][n1], al[0], bh1);
                MMA16816(acc[1][n0], al[1], bh0);
                MMA16816(acc[1][n1], al[1], bh1);
            }
        }
        __syncthreads();
        if (c + NSTAGE < NCHUNK) load_chunk(s, (c + NSTAGE) * 32);
    }

    if (mode == 0) {
        #pragma unroll
        for (int mf = 0; mf < 2; mf++) {
            int row = ctaM + wm * 32 + mf * 16 + (lane >> 2);
            #pragma unroll
            for (int nf = 0; nf < 8; nf++) {
                int col = ctaN + wn * 64 + nf * 8 + (lane & 3) * 2;
                float bx = 0.f, by = 0.f;
                if (bias) { bx = bias[col]; by = bias[col + 1]; }
                float2 v0 = {acc[mf][nf][0] + bx, acc[mf][nf][1] + by};
                float2 v1 = {acc[mf][nf][2] + bx, acc[mf][nf][3] + by};
                *(float2*)&C[(size_t)row * Ncols + col] = v0;
                *(float2*)&C[(size_t)(row + 8) * Ncols + col] = v1;
            }
        }
    } else {
        // split-write into per-head q/k/v bf16 hi/lo; q scaled by 0.125
        #pragma unroll
        for (int mf = 0; mf < 2; mf++) {
            int row = ctaM + wm * 32 + mf * 16 + (lane >> 2);
            int b = row >> 10, n = row & 1023;
            #pragma unroll
            for (int nf = 0; nf < 8; nf++) {
                int col = ctaN + wn * 64 + nf * 8 + (lane & 3) * 2;
                int s = col >> 10, hh = (col >> 6) & 15, dh = col & 63;
                float sc = (s == 0) ? 0.125f : 1.0f;
                __nv_bfloat16* hiP = (s == 0) ? qhi : (s == 1) ? khi : vhi;
                __nv_bfloat16* loP = (s == 0) ? qlo : (s == 1) ? klo : vlo;
                size_t o0 = (((size_t)(b * 16 + hh)) * 1024 + n) * 64 + dh;
                size_t o1 = o0 + 8 * 64;
                uint32_t lo;
                uint32_t hi = pack_split(
                    make_float2(acc[mf][nf][0] * sc, acc[mf][nf][1] * sc), lo);
                *(uint32_t*)&hiP[o0] = hi;
                *(uint32_t*)&loP[o0] = lo;
                hi = pack_split(
                    make_float2(acc[mf][nf][2] * sc, acc[mf][nf][3] * sc), lo);
                *(uint32_t*)&hiP[o1] = hi;
                *(uint32_t*)&loP[o1] = lo;
            }
        }
    }
}

// ---------------------------------------------------------------------------
// Tensor-core attention: CTA = (32-query tile, b*h). 8 warps.
// Phase1: S = Q K^T (bf16-split HMMA) -> fp32 smem.
// Phase2: masked softmax; S keeps UNNORMALIZED exp; attn written normalized.
// Phase3: O = exp(S) @ V, scaled by 1/rowsum in epilogue.
// ---------------------------------------------------------------------------
#define SROW 1036
#define SBYTES (32 * SROW * 4)             // 132608
#define KSTRIDE 144
#define STG_TILE (128 * KSTRIDE)           // 18432
#define STG_SIZE (2 * STG_TILE)
#define OFF_STG0 SBYTES
#define OFF_STG1 (SBYTES + STG_SIZE)
#define OFF_MASK (SBYTES + 2 * STG_SIZE)
#define OFF_INV  (OFF_MASK + 4096)
#define SMEM_ATTN (OFF_INV + 128)          // 210560

__global__ __launch_bounds__(256, 1) void attn_mma(
    const __nv_bfloat16* __restrict__ qhi, const __nv_bfloat16* __restrict__ qlo,
    const __nv_bfloat16* __restrict__ khi, const __nv_bfloat16* __restrict__ klo,
    const __nv_bfloat16* __restrict__ vhi, const __nv_bfloat16* __restrict__ vlo,
    const int* __restrict__ mask, float* __restrict__ attn,
    __nv_bfloat16* __restrict__ hhi, __nv_bfloat16* __restrict__ hlo)
{
    extern __shared__ char smem[];
    float* S = (float*)smem;
    const uint32_t sb = smem_u32(smem);
    const int tid = threadIdx.x, wid = tid >> 5, lane = tid & 31;
    const int q8 = lane >> 3, l8 = lane & 7;
    const int bh = blockIdx.y, b = bh >> 4, h = bh & 15;
    const int q0 = blockIdx.x * 32;
    const size_t head_base = (size_t)bh * Nn * DHn;

    auto load_tile = [&](const __nv_bfloat16* hiP, const __nv_bfloat16* loP,
                         int tile, uint32_t stgoff) {
        #pragma unroll 4
        for (int i = tid; i < 2048; i += 256) {
            int bsel = i >> 10, r = (i >> 3) & 127, c = i & 7;
            const __nv_bfloat16* src = (bsel ? loP : hiP) + head_base +
                                       (size_t)(tile * 128 + r) * 64 + c * 8;
            uint32_t dst = sb + stgoff + bsel * STG_TILE + r * KSTRIDE + c * 16;
            CP_ASYNC16(dst, __cvta_generic_to_global(src));
        }
        CP_COMMIT();
    };

    // stage Q (hi/lo) into stage1, K tile 0 into stage0
    #pragma unroll
    for (int i = tid; i < 512; i += 256) {
        int bsel = i >> 8, r = (i >> 3) & 31, c = i & 7;
        const __nv_bfloat16* src = (bsel ? qlo : qhi) + head_base +
                                   (size_t)(q0 + r) * 64 + c * 8;
        uint32_t dst = sb + OFF_STG1 + bsel * 4608 + r * KSTRIDE + c * 16;
        CP_ASYNC16(dst, __cvta_generic_to_global(src));
    }
    CP_COMMIT();
    load_tile(khi, klo, 0, OFF_STG0);

    {
        int4 mv = ((const int4*)(mask + b * Nn))[tid];
        ((int4*)(smem + OFF_MASK))[tid] = mv;
    }

    const int wm = wid & 1, wn = wid >> 1;

    uint32_t qfh[4][4], qfl[4][4];
    CP_WAIT1();
    __syncthreads();
    {
        uint32_t qhb = sb + OFF_STG1, qlb = sb + OFF_STG1 + 4608;
        #pragma unroll
        for (int kk = 0; kk < 4; kk++) {
            uint32_t ao = (uint32_t)((wm * 16 + (q8 & 1) * 8 + l8) * KSTRIDE +
                                     (q8 >> 1) * 16 + kk * 32);
            LDSM_X4(qfh[kk][0], qfh[kk][1], qfh[kk][2], qfh[kk][3], qhb + ao);
            LDSM_X4(qfl[kk][0], qfl[kk][1], qfl[kk][2], qfl[kk][3], qlb + ao);
        }
    }
    __syncthreads();
    load_tile(khi, klo, 1, OFF_STG1);

    // ---- Phase 1: S = Q K^T ----
    for (int kt = 0; kt < 8; kt++) {
        if (kt == 7) CP_WAIT0(); else CP_WAIT1();
        __syncthreads();
        uint32_t stg = sb + ((kt & 1) ? OFF_STG1 : OFF_STG0);
        uint32_t khb = stg, klb = stg + STG_TILE;

        float acc[4][4];
        #pragma unroll
        for (int i = 0; i < 4; i++)
            #pragma unroll
            for (int j = 0; j < 4; j++) acc[i][j] = 0.f;

        #pragma unroll
        for (int kk = 0; kk < 4; kk++) {
            uint32_t bfh[4][2], bfl[4][2];
            #pragma unroll
            for (int pr = 0; pr < 2; pr++) {
                uint32_t bo = (uint32_t)((wn * 32 + pr * 16 + (q8 >> 1) * 8 + l8) * KSTRIDE +
                                         (q8 & 1) * 16 + kk * 32);
                LDSM_X4(bfh[2*pr][0], bfh[2*pr][1], bfh[2*pr+1][0], bfh[2*pr+1][1], khb + bo);
                LDSM_X4(bfl[2*pr][0], bfl[2*pr][1], bfl[2*pr+1][0], bfl[2*pr+1][1], klb + bo);
            }
            #pragma unroll
            for (int nf = 0; nf < 4; nf++) MMA16816(acc[nf], qfh[kk], bfh[nf]);
            #pragma unroll
            for (int nf = 0; nf < 4; nf++) MMA16816(acc[nf], qfh[kk], bfl[nf]);
            #pragma unroll
            for (int nf = 0; nf < 4; nf++) MMA16816(acc[nf], qfl[kk], bfh[nf]);
        }
        int r0 = wm * 16 + (lane >> 2);
        #pragma unroll
        for (int nf = 0; nf < 4; nf++) {
            int col = kt * 128 + wn * 32 + nf * 8 + (lane & 3) * 2;
            *(float2*)&S[r0 * SROW + col]       = make_float2(acc[nf][0], acc[nf][1]);
            *(float2*)&S[(r0 + 8) * SROW + col] = make_float2(acc[nf][2], acc[nf][3]);
        }
        __syncthreads();
        if (kt + 2 < 8)      load_tile(khi, klo, kt + 2, (kt & 1) ? OFF_STG1 : OFF_STG0);
        else if (kt == 6)    load_tile(vhi, vlo, 0, OFF_STG0);
        else                 load_tile(vhi, vlo, 1, OFF_STG1);
    }

    // ---- Phase 2: masked softmax; keep UNNORMALIZED exp in S ----
    {
        const int4* msk4 = (const int4*)(smem + OFF_MASK);
        float* invs = (float*)(smem + OFF_INV);
        #pragma unroll
        for (int rr = 0; rr < 4; rr++) {
            int r = wid * 4 + rr;
            float* row = S + r * SROW;
            float mx = -3.4e38f;
            for (int k4 = lane; k4 < 256; k4 += 32) {
                float4 v = *(float4*)&row[k4 * 4];
                int4 m = msk4[k4];
                v.x = m.x ? v.x : NEGV; v.y = m.y ? v.y : NEGV;
                v.z = m.z ? v.z : NEGV; v.w = m.w ? v.w : NEGV;
                mx = fmaxf(mx, fmaxf(fmaxf(v.x, v.y), fmaxf(v.z, v.w)));
            }
            #pragma unroll
            for (int s = 16; s; s >>= 1) mx = fmaxf(mx, __shfl_xor_sync(0xffffffffu, mx, s));

            float sum = 0.f;
            for (int k4 = lane; k4 < 256; k4 += 32) {
                float4 v = *(float4*)&row[k4 * 4];
                int4 m = msk4[k4];
                v.x = m.x ? v.x : NEGV; v.y = m.y ? v.y : NEGV;
                v.z = m.z ? v.z : NEGV; v.w = m.w ? v.w : NEGV;
                v.x = __expf(v.x - mx); v.y = __expf(v.y - mx);
                v.z = __expf(v.z - mx); v.w = __expf(v.w - mx);
                sum += v.x + v.y + v.z + v.w;
                *(float4*)&row[k4 * 4] = v;
            }
            #pragma unroll
            for (int s = 16; s; s >>= 1) sum += __shfl_xor_sync(0xffffffffu, sum, s);

            float inv = 1.f / sum;
            if (lane == 0) invs[r] = inv;
            if (attn) {
                float* arow = attn + ((size_t)bh * Nn + q0 + r) * Nn;
                for (int k4 = lane; k4 < 256; k4 += 32) {
                    float4 v = *(float4*)&row[k4 * 4];
                    v.x *= inv; v.y *= inv; v.z *= inv; v.w *= inv;
                    *(float4*)&arow[k4 * 4] = v;
                }
            }
        }
    }
    __syncthreads();

    // ---- Phase 3: O = exp(S) V, scale by inv at end ----
    const int wm2 = wid & 1, wn2 = wid >> 1;
    float oacc[2][4];
    #pragma unroll
    for (int i = 0; i < 2; i++)
        #pragma unroll
        for (int j = 0; j < 4; j++) oacc[i][j] = 0.f;

    const int r0 = wm2 * 16 + (lane >> 2);
    for (int vt = 0; vt < 8; vt++) {
        if (vt == 7) CP_WAIT0(); else CP_WAIT1();
        __syncthreads();
        uint32_t stg = sb + ((vt & 1) ? OFF_STG1 : OFF_STG0);
        uint32_t vhb = stg, vlb = stg + STG_TILE;

        #pragma unroll
        for (int kk = 0; kk < 8; kk++) {
            int kc = vt * 128 + kk * 16 + (lane & 3) * 2;
            float2 p00 = *(float2*)&S[r0 * SROW + kc];
            float2 p01 = *(float2*)&S[r0 * SROW + kc + 8];
            float2 p10 = *(float2*)&S[(r0 + 8) * SROW + kc];
            float2 p11 = *(float2*)&S[(r0 + 8) * SROW + kc + 8];
            uint32_t ah[4], al[4];
            ah[0] = pack_split(p00, al[0]);
            ah[1] = pack_split(p10, al[1]);
            ah[2] = pack_split(p01, al[2]);
            ah[3] = pack_split(p11, al[3]);

            uint32_t vo = (uint32_t)((kk * 16 + (q8 & 1) * 8 + l8) * KSTRIDE +
                                     wn2 * 32 + (q8 >> 1) * 16);
            uint32_t bh0[2], bh1[2], bl0[2], bl1[2];
            LDSM_X4_T(bh0[0], bh0[1], bh1[0], bh1[1], vhb + vo);
            LDSM_X4_T(bl0[0], bl0[1], bl1[0], bl1[1], vlb + vo);

            MMA16816(oacc[0], ah, bh0);
            MMA16816(oacc[1], ah, bh1);
            MMA16816(oacc[0], ah, bl0);
            MMA16816(oacc[1], ah, bl1);
            MMA16816(oacc[0], al, bh0);
            MMA16816(oacc[1], al, bh1);
        }
        __syncthreads();
        if (vt + 2 < 8) load_tile(vhi, vlo, vt + 2, (vt & 1) ? OFF_STG1 : OFF_STG0);
    }

    // epilogue: scale by row inverse sums, write heads bf16 hi/lo
    const float* invs = (const float*)(smem + OFF_INV);
    float inv0 = invs[r0], inv1 = invs[r0 + 8];
    #pragma unroll
    for (int nt = 0; nt < 2; nt++) {
        int col = wn2 * 16 + nt * 8 + (lane & 3) * 2;
        size_t di0 = ((size_t)(b * Nn) + q0 + r0) * Dn + h * 64 + col;
        size_t di1 = di0 + 8 * Dn;
        uint32_t lo0, lo1;
        uint32_t hi0 = pack_split(make_float2(oacc[nt][0] * inv0, oacc[nt][1] * inv0), lo0);
        uint32_t hi1 = pack_split(make_float2(oacc[nt][2] * inv1, oacc[nt][3] * inv1), lo1);
        *(uint32_t*)&hhi[di0] = hi0;
        *(uint32_t*)&hlo[di0] = lo0;
        *(uint32_t*)&hhi[di1] = hi1;
        *(uint32_t*)&hlo[di1] = lo1;
    }
}

// ---------------------------------------------------------------------------

extern "C" void kernel_launch(void* const* d_in, const int* in_sizes, int n_in,
                              void* d_out, int out_size)
{
    const float* x     = (const float*)d_in[0];
    const int*   mask  = (const int*)d_in[1];
    const float* w_qkv = (const float*)d_in[2];
    const float* w_out = (const float*)d_in[3];
    const float* b_out = (const float*)d_in[4];

    float* out = (float*)d_out;
    const size_t out_elems  = (size_t)Bn * Nn * Dn;
    const size_t attn_elems = (size_t)Bn * Hn * Nn * Nn;
    float* attn = ((size_t)out_size >= out_elems + attn_elems) ? out + out_elems : nullptr;

    __nv_bfloat16 *xhi, *xlo, *wqkvThi, *wqkvTlo, *woutThi, *woutTlo, *hhi, *hlo;
    __nv_bfloat16 *qhi, *qlo, *khi, *klo, *vhi, *vlo;
    cudaGetSymbolAddress((void**)&xhi, g_xhi);
    cudaGetSymbolAddress((void**)&xlo, g_xlo);
    cudaGetSymbolAddress((void**)&wqkvThi, g_wqkvThi);
    cudaGetSymbolAddress((void**)&wqkvTlo, g_wqkvTlo);
    cudaGetSymbolAddress((void**)&woutThi, g_woutThi);
    cudaGetSymbolAddress((void**)&woutTlo, g_woutTlo);
    cudaGetSymbolAddress((void**)&hhi, g_hhi);
    cudaGetSymbolAddress((void**)&hlo, g_hlo);
    cudaGetSymbolAddress((void**)&qhi, g_qhi);
    cudaGetSymbolAddress((void**)&qlo, g_qlo);
    cudaGetSymbolAddress((void**)&khi, g_khi);
    cudaGetSymbolAddress((void**)&klo, g_klo);
    cudaGetSymbolAddress((void**)&vhi, g_vhi);
    cudaGetSymbolAddress((void**)&vlo, g_vlo);

    cudaFuncSetAttribute(gemm_mma, cudaFuncAttributeMaxDynamicSharedMemorySize, SMEM_GEMM);
    cudaFuncSetAttribute(attn_mma, cudaFuncAttributeMaxDynamicSharedMemorySize, SMEM_ATTN);

    const int n4x = (Bn * Nn * Dn) / 4;

    // 1) splits
    split_kernel<<<(n4x + 255) / 256, 256>>>((const float4*)x,
                                             (__nv_bfloat162*)xhi, (__nv_bfloat162*)xlo, n4x);
    splitT_kernel<<<dim3(D3 / 32, Dn / 32), dim3(32, 8)>>>(w_qkv, wqkvThi, wqkvTlo, Dn, D3);
    splitT_kernel<<<dim3(Dn / 32, Dn / 32), dim3(32, 8)>>>(w_out, woutThi, woutTlo, Dn, Dn);

    // 2) QKV projection, fused split into per-head q/k/v hi/lo
    gemm_mma<<<dim3(D3 / 128, (Bn * Nn) / 128), 256, SMEM_GEMM>>>(
        xhi, xlo, wqkvThi, wqkvTlo, nullptr, nullptr, D3, 1,
        qhi, qlo, khi, klo, vhi, vlo);

    // 3) tensor-core attention (writes attn + hhi/hlo)
    attn_mma<<<dim3(Nn / 32, Bn * Hn), 256, SMEM_ATTN>>>(
        qhi, qlo, khi, klo, vhi, vlo, mask, attn, hhi, hlo);

    // 4) output projection with bias
    gemm_mma<<<dim3(Dn / 128, (Bn * Nn) / 128), 256, SMEM_GEMM>>>(
        hhi, hlo, woutThi, woutTlo, out, b_out, Dn, 0,
        nullptr, nullptr, nullptr, nullptr, nullptr, nullptr);
}